// round 2
// baseline (speedup 1.0000x reference)
#include <cuda_runtime.h>
#include <cstddef>

// Problem constants (fixed shapes)
#define NB 8    // batch
#define CC 8    // channels
#define TT 600  // time frames
#define FF 513  // freq bins
#define TS 25   // T-split chunks
#define TCH (TT / TS)       // 24 frames per chunk
#define NPAIR 28            // C*(C-1)/2 off-diagonal pairs
#define NACC 64             // 8 diag + 28 re + 28 im

__device__ float g_part[(size_t)TS * NB * NACC * FF];   // ~26 MB partial covariances
__device__ float g_phi[(size_t)NB * NACC * FF];         // reduced covariances
__device__ float g_w[(size_t)NB * CC * 2 * FF];         // conj(w), [n][c][re/im][f]

__device__ __forceinline__ int pair_idx(int c, int e) { // c < e
    return c * 7 - (c * (c - 1)) / 2 + (e - c - 1);
}

// ---------------------------------------------------------------------------
// Kernel 1: partial spatial covariance of target, Hermitian storage.
// grid: (ceil(F/128), N, TS), block: (128, 2). threadIdx.y picks the half of
// the accumulator set (register-pressure split); both halves load all 16
// channel values (the duplicate hits L1).
// ---------------------------------------------------------------------------
template <int HALF>
__device__ __forceinline__ void cov_half(const float* __restrict__ xr,
                                         const float* __restrict__ xi,
                                         float* __restrict__ pb, int t0) {
    const size_t chanStride = (size_t)TT * FF;
    float dg[8];
    float pre[14], pim[14];
#pragma unroll
    for (int c = 0; c < 8; ++c) dg[c] = 0.f;
#pragma unroll
    for (int k = 0; k < 14; ++k) { pre[k] = 0.f; pim[k] = 0.f; }

#pragma unroll 2
    for (int t = t0; t < t0 + TCH; ++t) {
        float a[CC], b[CC];
        size_t toff = (size_t)t * FF;
#pragma unroll
        for (int c = 0; c < CC; ++c) {
            a[c] = xr[(size_t)c * chanStride + toff];
            b[c] = xi[(size_t)c * chanStride + toff];
        }
        if (HALF == 0) {
#pragma unroll
            for (int c = 0; c < CC; ++c) dg[c] += a[c] * a[c] + b[c] * b[c];
        }
#pragma unroll
        for (int c = 0; c < CC; ++c) {
#pragma unroll
            for (int e = c + 1; e < CC; ++e) {
                const int k = pair_idx(c, e);
                if ((HALF == 0 && k < 14) || (HALF == 1 && k >= 14)) {
                    const int kk = (HALF == 0) ? k : (k - 14);
                    pre[kk] += a[c] * a[e] + b[c] * b[e];
                    pim[kk] += b[c] * a[e] - a[c] * b[e];
                }
            }
        }
    }

    if (HALF == 0) {
#pragma unroll
        for (int c = 0; c < 8; ++c) pb[(size_t)c * FF] = dg[c];
#pragma unroll
        for (int k = 0; k < 14; ++k) {
            pb[(size_t)(8 + k) * FF] = pre[k];
            pb[(size_t)(36 + k) * FF] = pim[k];
        }
    } else {
#pragma unroll
        for (int k = 0; k < 14; ++k) {
            pb[(size_t)(8 + 14 + k) * FF] = pre[k];
            pb[(size_t)(36 + 14 + k) * FF] = pim[k];
        }
    }
}

__global__ void __launch_bounds__(256) cov_kernel(const float* __restrict__ x) {
    int f = blockIdx.x * 128 + threadIdx.x;
    int n = blockIdx.y;
    int z = blockIdx.z;
    if (f >= FF) return;

    const size_t chanStride = (size_t)TT * FF;
    const float* xr = x + (size_t)(n * 2 + 0) * CC * chanStride + f;
    const float* xi = x + (size_t)(n * 2 + 1) * CC * chanStride + f;
    float* pb = g_part + ((size_t)(z * NB + n) * NACC) * FF + f;
    int t0 = z * TCH;

    if (threadIdx.y == 0)
        cov_half<0>(xr, xi, pb, t0);
    else
        cov_half<1>(xr, xi, pb, t0);
}

// ---------------------------------------------------------------------------
// Kernel 2: reduce the TS partials. Thread per (n, k, f) — 295k threads.
// ---------------------------------------------------------------------------
__global__ void __launch_bounds__(256) reduce_kernel() {
    int id = blockIdx.x * 256 + threadIdx.x;
    const int TOT = NB * NACC * FF;
    if (id >= TOT) return;
    int f = id % FF;
    int rest = id / FF;      // n*NACC + k
    int k = rest % NACC;
    int n = rest / NACC;

    float s = 0.f;
#pragma unroll
    for (int z = 0; z < TS; ++z)
        s += g_part[((size_t)(z * NB + n) * NACC + k) * FF + f];
    g_phi[((size_t)(n * NACC + k)) * FF + f] = s;
}

// ---------------------------------------------------------------------------
// Kernel 3: MVDR weights from reduced covariance. Thread per (n, f).
// ---------------------------------------------------------------------------
__global__ void __launch_bounds__(128) weight_kernel(const float* __restrict__ sv) {
    int id = blockIdx.x * 128 + threadIdx.x;
    if (id >= NB * FF) return;
    int n = id / FF;
    int f = id - n * FF;

    float acc[NACC];
#pragma unroll
    for (int k = 0; k < NACC; ++k)
        acc[k] = g_phi[((size_t)(n * NACC + k)) * FF + f];

    const float invT = 1.0f / (float)TT;
    const float LOADC = 0.001f * 0.7071067811865475f;  // 0.001/sqrt(2)

    // steering vector d[f][c], layout [2, F, C, 1]
    float dr[CC], di[CC];
#pragma unroll
    for (int c = 0; c < CC; ++c) {
        dr[c] = sv[(size_t)(0 * FF + f) * CC + c];
        di[c] = sv[(size_t)(1 * FF + f) * CC + c];
    }

    // nume[c] = sum_e phi[c][e] * d[e] (phi Hermitian, complex loading on diag)
    float nr[CC], ni[CC];
#pragma unroll
    for (int c = 0; c < CC; ++c) {
        float pr = acc[c] * invT + LOADC;
        float pi = LOADC;
        float sr = pr * dr[c] - pi * di[c];
        float si = pr * di[c] + pi * dr[c];
#pragma unroll
        for (int e = 0; e < CC; ++e) {
            if (e == c) continue;
            float qr, qi;
            if (e > c) {
                int k = pair_idx(c, e);
                qr = acc[8 + k] * invT;
                qi = acc[36 + k] * invT;
            } else {
                int k = pair_idx(e, c);
                qr = acc[8 + k] * invT;
                qi = -acc[36 + k] * invT;
            }
            sr += qr * dr[e] - qi * di[e];
            si += qr * di[e] + qi * dr[e];
        }
        nr[c] = sr;
        ni[c] = si;
    }

    // deno = sum_c conj(d[c]) * nume[c]
    float der = 0.f, dei = 0.f;
#pragma unroll
    for (int c = 0; c < CC; ++c) {
        der += dr[c] * nr[c] + di[c] * ni[c];
        dei += dr[c] * ni[c] - di[c] * nr[c];
    }
    float inv = 1.0f / (der * der + dei * dei);

#pragma unroll
    for (int c = 0; c < CC; ++c) {
        float wr = (nr[c] * der + ni[c] * dei) * inv;
        float wi = (ni[c] * der - nr[c] * dei) * inv;
        // store conj(w)
        g_w[((size_t)(n * CC + c) * 2 + 0) * FF + f] = wr;
        g_w[((size_t)(n * CC + c) * 2 + 1) * FF + f] = -wi;
    }
}

// ---------------------------------------------------------------------------
// Kernel 4: beamform mixture with conj(w).
// grid: (ceil(F/128), T/TB, N), block 128. Thread owns one f, loops TB t's.
// ---------------------------------------------------------------------------
#define TB 4
__global__ void __launch_bounds__(128) bf_kernel(const float* __restrict__ y,
                                                 float* __restrict__ out) {
    int f = blockIdx.x * 128 + threadIdx.x;
    int n = blockIdx.z;
    int t0 = blockIdx.y * TB;
    if (f >= FF) return;

    float cwr[CC], cwi[CC];
#pragma unroll
    for (int c = 0; c < CC; ++c) {
        cwr[c] = g_w[((size_t)(n * CC + c) * 2 + 0) * FF + f];
        cwi[c] = g_w[((size_t)(n * CC + c) * 2 + 1) * FF + f];
    }

    const size_t chanStride = (size_t)TT * FF;
    const float* yr = y + (size_t)(n * 2 + 0) * CC * chanStride + f;
    const float* yi = y + (size_t)(n * 2 + 1) * CC * chanStride + f;
    float* outr = out + (size_t)(n * 2 + 0) * TT * FF + f;
    float* outi = out + (size_t)(n * 2 + 1) * TT * FF + f;

#pragma unroll
    for (int t = t0; t < t0 + TB; ++t) {
        size_t toff = (size_t)t * FF;
        float ar = 0.f, ai = 0.f;
#pragma unroll
        for (int c = 0; c < CC; ++c) {
            float a = yr[(size_t)c * chanStride + toff];
            float b = yi[(size_t)c * chanStride + toff];
            ar += cwr[c] * a - cwi[c] * b;
            ai += cwr[c] * b + cwi[c] * a;
        }
        outr[toff] = ar;
        outi[toff] = ai;
    }
}

extern "C" void kernel_launch(void* const* d_in, const int* in_sizes, int n_in,
                              void* d_out, int out_size) {
    const float* mixture = (const float*)d_in[0];
    // d_in[1] = noise (unused by the reference computation)
    const float* target = (const float*)d_in[2];
    const float* sv = (const float*)d_in[3];
    float* out = (float*)d_out;

    dim3 gA((FF + 127) / 128, NB, TS);
    cov_kernel<<<gA, dim3(128, 2)>>>(target);

    int nr = NB * NACC * FF;
    reduce_kernel<<<(nr + 255) / 256, 256>>>();

    int nw = NB * FF;
    weight_kernel<<<(nw + 127) / 128, 128>>>(sv);

    dim3 gC((FF + 127) / 128, TT / TB, NB);
    bf_kernel<<<gC, 128>>>(mixture, out);
}

// round 3
// speedup vs baseline: 1.1257x; 1.1257x over previous
#include <cuda_runtime.h>
#include <cstddef>

// Problem constants (fixed shapes)
#define NB 8    // batch
#define CC 8    // channels
#define TT 600  // time frames
#define FF 513  // freq bins
#define TS 20   // T-split chunks
#define TCH (TT / TS)       // 30 frames per chunk
#define NPAIR 28            // C*(C-1)/2 off-diagonal pairs
#define NACC 64             // 8 diag + 28 re + 28 im

__device__ float g_part[(size_t)TS * NB * NACC * FF];   // ~21 MB partial covariances
__device__ float g_phi[(size_t)NB * NACC * FF];         // reduced covariances
__device__ float g_w[(size_t)NB * CC * 2 * FF];         // conj(w), [n][c][re/im][f]

__device__ __forceinline__ int pair_idx(int c, int e) { // c < e
    return c * 7 - (c * (c - 1)) / 2 + (e - c - 1);
}

// ---------------------------------------------------------------------------
// Kernel 1: partial spatial covariance of target, Hermitian storage.
// grid: (ceil(F/128), N, TS), block: 128. Thread owns one f, full accumulator
// set in registers (round-1 structure; TS=20 fixes grid starvation).
// ---------------------------------------------------------------------------
__global__ void __launch_bounds__(128) cov_kernel(const float* __restrict__ x) {
    int f = blockIdx.x * 128 + threadIdx.x;
    int n = blockIdx.y;
    int z = blockIdx.z;
    if (f >= FF) return;

    float diag[CC];
    float ore[NPAIR], oim[NPAIR];
#pragma unroll
    for (int c = 0; c < CC; ++c) diag[c] = 0.f;
#pragma unroll
    for (int k = 0; k < NPAIR; ++k) { ore[k] = 0.f; oim[k] = 0.f; }

    const size_t chanStride = (size_t)TT * FF;
    const float* xr = x + (size_t)(n * 2 + 0) * CC * chanStride + f;
    const float* xi = x + (size_t)(n * 2 + 1) * CC * chanStride + f;

    int t0 = z * TCH;
#pragma unroll 2
    for (int t = t0; t < t0 + TCH; ++t) {
        float a[CC], b[CC];
        size_t toff = (size_t)t * FF;
#pragma unroll
        for (int c = 0; c < CC; ++c) {
            a[c] = xr[(size_t)c * chanStride + toff];
            b[c] = xi[(size_t)c * chanStride + toff];
        }
#pragma unroll
        for (int c = 0; c < CC; ++c) diag[c] += a[c] * a[c] + b[c] * b[c];
        int k = 0;
#pragma unroll
        for (int c = 0; c < CC; ++c) {
#pragma unroll
            for (int e = c + 1; e < CC; ++e, ++k) {
                // phi[c][e] += x[c] * conj(x[e])
                ore[k] += a[c] * a[e] + b[c] * b[e];
                oim[k] += b[c] * a[e] - a[c] * b[e];
            }
        }
    }

    float* pb = g_part + ((size_t)(z * NB + n) * NACC) * FF + f;
#pragma unroll
    for (int c = 0; c < CC; ++c) pb[(size_t)c * FF] = diag[c];
#pragma unroll
    for (int k = 0; k < NPAIR; ++k) {
        pb[(size_t)(8 + k) * FF] = ore[k];
        pb[(size_t)(36 + k) * FF] = oim[k];
    }
}

// ---------------------------------------------------------------------------
// Kernel 2: reduce the TS partials. Thread per (n, k, f).
// ---------------------------------------------------------------------------
__global__ void __launch_bounds__(256) reduce_kernel() {
    int id = blockIdx.x * 256 + threadIdx.x;
    const int TOT = NB * NACC * FF;
    if (id >= TOT) return;
    int f = id % FF;
    int rest = id / FF;      // n*NACC + k
    int k = rest % NACC;
    int n = rest / NACC;

    float s = 0.f;
#pragma unroll
    for (int z = 0; z < TS; ++z)
        s += g_part[((size_t)(z * NB + n) * NACC + k) * FF + f];
    g_phi[((size_t)(n * NACC + k)) * FF + f] = s;
}

// ---------------------------------------------------------------------------
// Kernel 3: MVDR weights from reduced covariance. Thread per (n, f).
// ---------------------------------------------------------------------------
__global__ void __launch_bounds__(128) weight_kernel(const float* __restrict__ sv) {
    int id = blockIdx.x * 128 + threadIdx.x;
    if (id >= NB * FF) return;
    int n = id / FF;
    int f = id - n * FF;

    float acc[NACC];
#pragma unroll
    for (int k = 0; k < NACC; ++k)
        acc[k] = g_phi[((size_t)(n * NACC + k)) * FF + f];

    const float invT = 1.0f / (float)TT;
    const float LOADC = 0.001f * 0.7071067811865475f;  // 0.001/sqrt(2)

    // steering vector d[f][c], layout [2, F, C, 1]
    float dr[CC], di[CC];
#pragma unroll
    for (int c = 0; c < CC; ++c) {
        dr[c] = sv[(size_t)(0 * FF + f) * CC + c];
        di[c] = sv[(size_t)(1 * FF + f) * CC + c];
    }

    // nume[c] = sum_e phi[c][e] * d[e] (phi Hermitian, complex loading on diag)
    float nr[CC], ni[CC];
#pragma unroll
    for (int c = 0; c < CC; ++c) {
        float pr = acc[c] * invT + LOADC;
        float pi = LOADC;
        float sr = pr * dr[c] - pi * di[c];
        float si = pr * di[c] + pi * dr[c];
#pragma unroll
        for (int e = 0; e < CC; ++e) {
            if (e == c) continue;
            float qr, qi;
            if (e > c) {
                int k = pair_idx(c, e);
                qr = acc[8 + k] * invT;
                qi = acc[36 + k] * invT;
            } else {
                int k = pair_idx(e, c);
                qr = acc[8 + k] * invT;
                qi = -acc[36 + k] * invT;
            }
            sr += qr * dr[e] - qi * di[e];
            si += qr * di[e] + qi * dr[e];
        }
        nr[c] = sr;
        ni[c] = si;
    }

    // deno = sum_c conj(d[c]) * nume[c]
    float der = 0.f, dei = 0.f;
#pragma unroll
    for (int c = 0; c < CC; ++c) {
        der += dr[c] * nr[c] + di[c] * ni[c];
        dei += dr[c] * ni[c] - di[c] * nr[c];
    }
    float inv = 1.0f / (der * der + dei * dei);

#pragma unroll
    for (int c = 0; c < CC; ++c) {
        float wr = (nr[c] * der + ni[c] * dei) * inv;
        float wi = (ni[c] * der - nr[c] * dei) * inv;
        // store conj(w)
        g_w[((size_t)(n * CC + c) * 2 + 0) * FF + f] = wr;
        g_w[((size_t)(n * CC + c) * 2 + 1) * FF + f] = -wi;
    }
}

// ---------------------------------------------------------------------------
// Kernel 4: beamform mixture with conj(w). Software-pipelined: prefetch the
// next t's 16 channel values while computing the current t (raises per-warp
// MLP — the round-2 profile showed issue=12.9% with regs=32, i.e. MLP-starved).
// grid: (ceil(F/128), T/TB, N), block 128.
// ---------------------------------------------------------------------------
#define TB 8
__global__ void bf_kernel(const float* __restrict__ y,
                          float* __restrict__ out) {
    int f = blockIdx.x * 128 + threadIdx.x;
    int n = blockIdx.z;
    int t0 = blockIdx.y * TB;
    if (f >= FF) return;

    float cwr[CC], cwi[CC];
#pragma unroll
    for (int c = 0; c < CC; ++c) {
        cwr[c] = g_w[((size_t)(n * CC + c) * 2 + 0) * FF + f];
        cwi[c] = g_w[((size_t)(n * CC + c) * 2 + 1) * FF + f];
    }

    const size_t chanStride = (size_t)TT * FF;
    const float* yr = y + (size_t)(n * 2 + 0) * CC * chanStride + f;
    const float* yi = y + (size_t)(n * 2 + 1) * CC * chanStride + f;
    float* outr = out + (size_t)(n * 2 + 0) * TT * FF + f;
    float* outi = out + (size_t)(n * 2 + 1) * TT * FF + f;

    float a[CC], b[CC];
    {
        size_t toff = (size_t)t0 * FF;
#pragma unroll
        for (int c = 0; c < CC; ++c) {
            a[c] = yr[(size_t)c * chanStride + toff];
            b[c] = yi[(size_t)c * chanStride + toff];
        }
    }

#pragma unroll
    for (int i = 0; i < TB; ++i) {
        float na[CC], nb[CC];
        if (i < TB - 1) {
            size_t toff2 = (size_t)(t0 + i + 1) * FF;
#pragma unroll
            for (int c = 0; c < CC; ++c) {
                na[c] = yr[(size_t)c * chanStride + toff2];
                nb[c] = yi[(size_t)c * chanStride + toff2];
            }
        }

        float ar = 0.f, ai = 0.f;
#pragma unroll
        for (int c = 0; c < CC; ++c) {
            // conj(w) * y : (cwr + i cwi)(a + i b)
            ar += cwr[c] * a[c] - cwi[c] * b[c];
            ai += cwr[c] * b[c] + cwi[c] * a[c];
        }
        size_t toff = (size_t)(t0 + i) * FF;
        outr[toff] = ar;
        outi[toff] = ai;

        if (i < TB - 1) {
#pragma unroll
            for (int c = 0; c < CC; ++c) { a[c] = na[c]; b[c] = nb[c]; }
        }
    }
}

extern "C" void kernel_launch(void* const* d_in, const int* in_sizes, int n_in,
                              void* d_out, int out_size) {
    const float* mixture = (const float*)d_in[0];
    // d_in[1] = noise (unused by the reference computation)
    const float* target = (const float*)d_in[2];
    const float* sv = (const float*)d_in[3];
    float* out = (float*)d_out;

    dim3 gA((FF + 127) / 128, NB, TS);
    cov_kernel<<<gA, 128>>>(target);

    int nr = NB * NACC * FF;
    reduce_kernel<<<(nr + 255) / 256, 256>>>();

    int nw = NB * FF;
    weight_kernel<<<(nw + 127) / 128, 128>>>(sv);

    dim3 gC((FF + 127) / 128, TT / TB, NB);
    bf_kernel<<<gC, 128>>>(mixture, out);
}

// round 4
// speedup vs baseline: 1.1679x; 1.0375x over previous
#include <cuda_runtime.h>
#include <cstddef>

// Problem constants (fixed shapes)
#define NB 8    // batch
#define CC 8    // channels
#define TT 600  // time frames
#define FF 513  // freq bins
#define TS 20   // T-split chunks
#define TCH (TT / TS)       // 30 frames per chunk
#define NP 17               // partial entries: 8 re(nume) + 8 im(nume) + |s|^2

__device__ float g_part[(size_t)TS * NB * NP * FF];  // ~5.6 MB partials
__device__ float g_w[(size_t)NB * CC * 2 * FF];      // conj(w), [n][c][re/im][f]

// ---------------------------------------------------------------------------
// Kernel 1: partial accumulation of nume = sum_t x * s and den = sum_t |s|^2,
// where s_t = sum_e conj(x_e[t]) d_e.  (phi is never materialized — the MVDR
// quotient only needs phi*d and d^H phi d.)
// grid: (ceil(NB*FF/128), TS), block 128. One thread per (n,f,z).
// ---------------------------------------------------------------------------
__global__ void snum_kernel(const float* __restrict__ x,
                            const float* __restrict__ sv) {
    int id = blockIdx.x * 128 + threadIdx.x;  // over NB*FF
    int z = blockIdx.y;
    if (id >= NB * FF) return;
    int n = id / FF;
    int f = id - n * FF;

    // steering vector d[f][c], layout [2, F, C, 1]
    float dr[CC], di[CC];
#pragma unroll
    for (int c = 0; c < CC; ++c) {
        dr[c] = sv[(size_t)(0 * FF + f) * CC + c];
        di[c] = sv[(size_t)(1 * FF + f) * CC + c];
    }

    float numr[CC], numi[CC], den = 0.f;
#pragma unroll
    for (int c = 0; c < CC; ++c) { numr[c] = 0.f; numi[c] = 0.f; }

    const size_t chanStride = (size_t)TT * FF;
    const float* xr = x + (size_t)(n * 2 + 0) * CC * chanStride + f;
    const float* xi = x + (size_t)(n * 2 + 1) * CC * chanStride + f;

    int t0 = z * TCH;
    float a[CC], b[CC];
    {
        size_t toff = (size_t)t0 * FF;
#pragma unroll
        for (int c = 0; c < CC; ++c) {
            a[c] = xr[(size_t)c * chanStride + toff];
            b[c] = xi[(size_t)c * chanStride + toff];
        }
    }

#pragma unroll 2
    for (int i = 0; i < TCH; ++i) {
        float na[CC], nb[CC];
        if (i < TCH - 1) {
            size_t toff2 = (size_t)(t0 + i + 1) * FF;
#pragma unroll
            for (int c = 0; c < CC; ++c) {
                na[c] = xr[(size_t)c * chanStride + toff2];
                nb[c] = xi[(size_t)c * chanStride + toff2];
            }
        }

        // s = sum_c conj(x_c) d_c
        float sr = 0.f, si = 0.f;
#pragma unroll
        for (int c = 0; c < CC; ++c) {
            sr += a[c] * dr[c] + b[c] * di[c];
            si += a[c] * di[c] - b[c] * dr[c];
        }
        den += sr * sr + si * si;
        // nume_c += x_c * s
#pragma unroll
        for (int c = 0; c < CC; ++c) {
            numr[c] += a[c] * sr - b[c] * si;
            numi[c] += a[c] * si + b[c] * sr;
        }

        if (i < TCH - 1) {
#pragma unroll
            for (int c = 0; c < CC; ++c) { a[c] = na[c]; b[c] = nb[c]; }
        }
    }

    float* pb = g_part + ((size_t)(z * NB + n) * NP) * FF + f;
#pragma unroll
    for (int c = 0; c < CC; ++c) {
        pb[(size_t)c * FF] = numr[c];
        pb[(size_t)(8 + c) * FF] = numi[c];
    }
    pb[(size_t)16 * FF] = den;
}

// ---------------------------------------------------------------------------
// Kernel 2: reduce partials, add diagonal loading, form conj(w).
// One thread per (n, f).
// ---------------------------------------------------------------------------
__global__ void __launch_bounds__(128) weight_kernel(const float* __restrict__ sv) {
    int id = blockIdx.x * 128 + threadIdx.x;
    if (id >= NB * FF) return;
    int n = id / FF;
    int f = id - n * FF;

    float numr[CC], numi[CC], den = 0.f;
#pragma unroll
    for (int c = 0; c < CC; ++c) { numr[c] = 0.f; numi[c] = 0.f; }
#pragma unroll
    for (int z = 0; z < TS; ++z) {
        const float* pb = g_part + ((size_t)(z * NB + n) * NP) * FF + f;
#pragma unroll
        for (int c = 0; c < CC; ++c) {
            numr[c] += pb[(size_t)c * FF];
            numi[c] += pb[(size_t)(8 + c) * FF];
        }
        den += pb[(size_t)16 * FF];
    }

    const float invT = 1.0f / (float)TT;
    const float LOADC = 0.001f * 0.7071067811865475f;  // 0.001/sqrt(2)

    float dr[CC], di[CC];
    float dd = 0.f;
#pragma unroll
    for (int c = 0; c < CC; ++c) {
        dr[c] = sv[(size_t)(0 * FF + f) * CC + c];
        di[c] = sv[(size_t)(1 * FF + f) * CC + c];
        dd += dr[c] * dr[c] + di[c] * di[c];
    }

    // nume_c = invT * sum + LOAD*(1+i)*d_c
    float nr[CC], ni[CC];
#pragma unroll
    for (int c = 0; c < CC; ++c) {
        nr[c] = numr[c] * invT + LOADC * (dr[c] - di[c]);
        ni[c] = numi[c] * invT + LOADC * (dr[c] + di[c]);
    }
    // deno = invT * sum|s|^2 + LOAD*(1+i)*||d||^2
    float der = den * invT + LOADC * dd;
    float dei = LOADC * dd;
    float inv = 1.0f / (der * der + dei * dei);

#pragma unroll
    for (int c = 0; c < CC; ++c) {
        float wr = (nr[c] * der + ni[c] * dei) * inv;
        float wi = (ni[c] * der - nr[c] * dei) * inv;
        // store conj(w)
        g_w[((size_t)(n * CC + c) * 2 + 0) * FF + f] = wr;
        g_w[((size_t)(n * CC + c) * 2 + 1) * FF + f] = -wi;
    }
}

// ---------------------------------------------------------------------------
// Kernel 3: beamform mixture with conj(w). Depth-2 software pipeline
// (32 loads in flight per warp).
// grid: (ceil(F/128), T/TB, N), block 128.
// ---------------------------------------------------------------------------
#define TB 8
__global__ void bf_kernel(const float* __restrict__ y,
                          float* __restrict__ out) {
    int f = blockIdx.x * 128 + threadIdx.x;
    int n = blockIdx.z;
    int t0 = blockIdx.y * TB;
    if (f >= FF) return;

    float cwr[CC], cwi[CC];
#pragma unroll
    for (int c = 0; c < CC; ++c) {
        cwr[c] = g_w[((size_t)(n * CC + c) * 2 + 0) * FF + f];
        cwi[c] = g_w[((size_t)(n * CC + c) * 2 + 1) * FF + f];
    }

    const size_t chanStride = (size_t)TT * FF;
    const float* yr = y + (size_t)(n * 2 + 0) * CC * chanStride + f;
    const float* yi = y + (size_t)(n * 2 + 1) * CC * chanStride + f;
    float* outr = out + (size_t)(n * 2 + 0) * TT * FF + f;
    float* outi = out + (size_t)(n * 2 + 1) * TT * FF + f;

    float a[2][CC], b[2][CC];
#pragma unroll
    for (int s = 0; s < 2; ++s) {
        size_t toff = (size_t)(t0 + s) * FF;
#pragma unroll
        for (int c = 0; c < CC; ++c) {
            a[s][c] = yr[(size_t)c * chanStride + toff];
            b[s][c] = yi[(size_t)c * chanStride + toff];
        }
    }

#pragma unroll
    for (int i = 0; i < TB; ++i) {
        const int s = i & 1;
        float na[CC], nb[CC];
        if (i < TB - 2) {
            size_t toff2 = (size_t)(t0 + i + 2) * FF;
#pragma unroll
            for (int c = 0; c < CC; ++c) {
                na[c] = yr[(size_t)c * chanStride + toff2];
                nb[c] = yi[(size_t)c * chanStride + toff2];
            }
        }

        float ar = 0.f, ai = 0.f;
#pragma unroll
        for (int c = 0; c < CC; ++c) {
            ar += cwr[c] * a[s][c] - cwi[c] * b[s][c];
            ai += cwr[c] * b[s][c] + cwi[c] * a[s][c];
        }
        size_t toff = (size_t)(t0 + i) * FF;
        outr[toff] = ar;
        outi[toff] = ai;

        if (i < TB - 2) {
#pragma unroll
            for (int c = 0; c < CC; ++c) { a[s][c] = na[c]; b[s][c] = nb[c]; }
        }
    }
}

extern "C" void kernel_launch(void* const* d_in, const int* in_sizes, int n_in,
                              void* d_out, int out_size) {
    const float* mixture = (const float*)d_in[0];
    // d_in[1] = noise (unused by the reference computation)
    const float* target = (const float*)d_in[2];
    const float* sv = (const float*)d_in[3];
    float* out = (float*)d_out;

    int nth = NB * FF;  // 4104
    dim3 gA((nth + 127) / 128, TS);
    snum_kernel<<<gA, 128>>>(target, sv);

    weight_kernel<<<(nth + 127) / 128, 128>>>(sv);

    dim3 gC((FF + 127) / 128, TT / TB, NB);
    bf_kernel<<<gC, 128>>>(mixture, out);
}

// round 5
// speedup vs baseline: 1.3095x; 1.1212x over previous
#include <cuda_runtime.h>
#include <cstddef>

// Problem constants (fixed shapes)
#define NB 8    // batch
#define CC 8    // channels
#define TT 600  // time frames
#define FF 513  // freq bins
#define TS 30   // T-split chunks (must be <= 32 for the warp-reduce)
#define TCH (TT / TS)       // 20 frames per chunk
#define NP 17               // partial entries: 8 re(nume) + 8 im(nume) + |s|^2

__device__ float g_part[(size_t)TS * NB * NP * FF];  // ~8.4 MB partials
__device__ float g_w[(size_t)NB * CC * 2 * FF];      // conj(w), [n][c][re/im][f]

// ---------------------------------------------------------------------------
// Kernel 1: partial accumulation of nume = sum_t x * s and den = sum_t |s|^2,
// where s_t = sum_e conj(x_e[t]) d_e.  (phi never materialized.)
// grid: (ceil(NB*FF/128), TS), block 128. One thread per (n,f,z).
// ---------------------------------------------------------------------------
__global__ void snum_kernel(const float* __restrict__ x,
                            const float* __restrict__ sv) {
    int id = blockIdx.x * 128 + threadIdx.x;  // over NB*FF
    int z = blockIdx.y;
    if (id >= NB * FF) return;
    int n = id / FF;
    int f = id - n * FF;

    // steering vector d[f][c], layout [2, F, C, 1]
    float dr[CC], di[CC];
#pragma unroll
    for (int c = 0; c < CC; ++c) {
        dr[c] = sv[(size_t)(0 * FF + f) * CC + c];
        di[c] = sv[(size_t)(1 * FF + f) * CC + c];
    }

    float numr[CC], numi[CC], den = 0.f;
#pragma unroll
    for (int c = 0; c < CC; ++c) { numr[c] = 0.f; numi[c] = 0.f; }

    const size_t chanStride = (size_t)TT * FF;
    const float* xr = x + (size_t)(n * 2 + 0) * CC * chanStride + f;
    const float* xi = x + (size_t)(n * 2 + 1) * CC * chanStride + f;

    int t0 = z * TCH;
    float a[CC], b[CC];
    {
        size_t toff = (size_t)t0 * FF;
#pragma unroll
        for (int c = 0; c < CC; ++c) {
            a[c] = xr[(size_t)c * chanStride + toff];
            b[c] = xi[(size_t)c * chanStride + toff];
        }
    }

#pragma unroll 2
    for (int i = 0; i < TCH; ++i) {
        float na[CC], nb[CC];
        if (i < TCH - 1) {
            size_t toff2 = (size_t)(t0 + i + 1) * FF;
#pragma unroll
            for (int c = 0; c < CC; ++c) {
                na[c] = xr[(size_t)c * chanStride + toff2];
                nb[c] = xi[(size_t)c * chanStride + toff2];
            }
        }

        // s = sum_c conj(x_c) d_c
        float sr = 0.f, si = 0.f;
#pragma unroll
        for (int c = 0; c < CC; ++c) {
            sr += a[c] * dr[c] + b[c] * di[c];
            si += a[c] * di[c] - b[c] * dr[c];
        }
        den += sr * sr + si * si;
        // nume_c += x_c * s
#pragma unroll
        for (int c = 0; c < CC; ++c) {
            numr[c] += a[c] * sr - b[c] * si;
            numi[c] += a[c] * si + b[c] * sr;
        }

        if (i < TCH - 1) {
#pragma unroll
            for (int c = 0; c < CC; ++c) { a[c] = na[c]; b[c] = nb[c]; }
        }
    }

    float* pb = g_part + ((size_t)(z * NB + n) * NP) * FF + f;
#pragma unroll
    for (int c = 0; c < CC; ++c) {
        pb[(size_t)c * FF] = numr[c];
        pb[(size_t)(8 + c) * FF] = numi[c];
    }
    pb[(size_t)16 * FF] = den;
}

// ---------------------------------------------------------------------------
// Kernel 2: warp per (n,f). Lane z loads that chunk's 17 partials; butterfly
// shuffle reduction; lane 0 applies loading and solves for conj(w).
// block 256 (8 warps) -> 513 blocks total.
// ---------------------------------------------------------------------------
__global__ void __launch_bounds__(256) weight_kernel(const float* __restrict__ sv) {
    int gw = (blockIdx.x * 256 + threadIdx.x) >> 5;  // global warp id
    int lane = threadIdx.x & 31;
    if (gw >= NB * FF) return;
    int n = gw / FF;
    int f = gw - n * FF;

    float v[NP];
    if (lane < TS) {
        const float* pb = g_part + ((size_t)(lane * NB + n) * NP) * FF + f;
#pragma unroll
        for (int k = 0; k < NP; ++k) v[k] = pb[(size_t)k * FF];
    } else {
#pragma unroll
        for (int k = 0; k < NP; ++k) v[k] = 0.f;
    }

#pragma unroll
    for (int off = 16; off >= 1; off >>= 1) {
#pragma unroll
        for (int k = 0; k < NP; ++k)
            v[k] += __shfl_down_sync(0xffffffffu, v[k], off);
    }

    if (lane != 0) return;

    const float invT = 1.0f / (float)TT;
    const float LOADC = 0.001f * 0.7071067811865475f;  // 0.001/sqrt(2)

    float dr[CC], di[CC];
    float dd = 0.f;
#pragma unroll
    for (int c = 0; c < CC; ++c) {
        dr[c] = sv[(size_t)(0 * FF + f) * CC + c];
        di[c] = sv[(size_t)(1 * FF + f) * CC + c];
        dd += dr[c] * dr[c] + di[c] * di[c];
    }

    // nume_c = invT*sum + LOAD*(1+i)*d_c
    float nr[CC], ni[CC];
#pragma unroll
    for (int c = 0; c < CC; ++c) {
        nr[c] = v[c] * invT + LOADC * (dr[c] - di[c]);
        ni[c] = v[8 + c] * invT + LOADC * (dr[c] + di[c]);
    }
    // deno = invT*sum|s|^2 + LOAD*(1+i)*||d||^2
    float der = v[16] * invT + LOADC * dd;
    float dei = LOADC * dd;
    float inv = 1.0f / (der * der + dei * dei);

#pragma unroll
    for (int c = 0; c < CC; ++c) {
        float wr = (nr[c] * der + ni[c] * dei) * inv;
        float wi = (ni[c] * der - nr[c] * dei) * inv;
        g_w[((size_t)(n * CC + c) * 2 + 0) * FF + f] = wr;   // re(conj w)
        g_w[((size_t)(n * CC + c) * 2 + 1) * FF + f] = -wi;  // im(conj w)
    }
}

// ---------------------------------------------------------------------------
// Kernel 3: beamform mixture with conj(w). Depth-3 prefetch ring
// (up to 48 loads in flight per warp).
// grid: (ceil(F/128), T/TB, N), block 128.
// ---------------------------------------------------------------------------
#define TB 8
#define DEPTH 3
__global__ void bf_kernel(const float* __restrict__ y,
                          float* __restrict__ out) {
    int f = blockIdx.x * 128 + threadIdx.x;
    int n = blockIdx.z;
    int t0 = blockIdx.y * TB;
    if (f >= FF) return;

    float cwr[CC], cwi[CC];
#pragma unroll
    for (int c = 0; c < CC; ++c) {
        cwr[c] = g_w[((size_t)(n * CC + c) * 2 + 0) * FF + f];
        cwi[c] = g_w[((size_t)(n * CC + c) * 2 + 1) * FF + f];
    }

    const size_t chanStride = (size_t)TT * FF;
    const float* yr = y + (size_t)(n * 2 + 0) * CC * chanStride + f;
    const float* yi = y + (size_t)(n * 2 + 1) * CC * chanStride + f;
    float* outr = out + (size_t)(n * 2 + 0) * TT * FF + f;
    float* outi = out + (size_t)(n * 2 + 1) * TT * FF + f;

    float a[DEPTH][CC], b[DEPTH][CC];
#pragma unroll
    for (int s = 0; s < DEPTH; ++s) {
        size_t toff = (size_t)(t0 + s) * FF;
#pragma unroll
        for (int c = 0; c < CC; ++c) {
            a[s][c] = yr[(size_t)c * chanStride + toff];
            b[s][c] = yi[(size_t)c * chanStride + toff];
        }
    }

#pragma unroll
    for (int i = 0; i < TB; ++i) {
        const int s = i % DEPTH;
        float na[CC], nb[CC];
        if (i < TB - DEPTH) {
            size_t toff2 = (size_t)(t0 + i + DEPTH) * FF;
#pragma unroll
            for (int c = 0; c < CC; ++c) {
                na[c] = yr[(size_t)c * chanStride + toff2];
                nb[c] = yi[(size_t)c * chanStride + toff2];
            }
        }

        float ar = 0.f, ai = 0.f;
#pragma unroll
        for (int c = 0; c < CC; ++c) {
            ar += cwr[c] * a[s][c] - cwi[c] * b[s][c];
            ai += cwr[c] * b[s][c] + cwi[c] * a[s][c];
        }
        size_t toff = (size_t)(t0 + i) * FF;
        outr[toff] = ar;
        outi[toff] = ai;

        if (i < TB - DEPTH) {
#pragma unroll
            for (int c = 0; c < CC; ++c) { a[s][c] = na[c]; b[s][c] = nb[c]; }
        }
    }
}

extern "C" void kernel_launch(void* const* d_in, const int* in_sizes, int n_in,
                              void* d_out, int out_size) {
    const float* mixture = (const float*)d_in[0];
    // d_in[1] = noise (unused by the reference computation)
    const float* target = (const float*)d_in[2];
    const float* sv = (const float*)d_in[3];
    float* out = (float*)d_out;

    int nth = NB * FF;  // 4104
    dim3 gA((nth + 127) / 128, TS);
    snum_kernel<<<gA, 128>>>(target, sv);

    int nwarps = nth;  // one warp per (n,f)
    weight_kernel<<<(nwarps * 32 + 255) / 256, 256>>>(sv);

    dim3 gC((FF + 127) / 128, TT / TB, NB);
    bf_kernel<<<gC, 128>>>(mixture, out);
}

// round 6
// speedup vs baseline: 1.4122x; 1.0784x over previous
#include <cuda_runtime.h>
#include <cstddef>

// Problem constants (fixed shapes)
#define NB 8    // batch
#define CC 8    // channels
#define TT 600  // time frames
#define FF 513  // freq bins
#define TS 20   // T-split chunks (<= 32 for the warp-reduce)
#define TCH (TT / TS)       // 30 frames per chunk
#define NP 17               // partial entries: 8 re(nume) + 8 im(nume) + |s|^2

__device__ float g_part[(size_t)TS * NB * NP * FF];  // ~5.6 MB partials
__device__ float g_w[(size_t)NB * CC * 2 * FF];      // conj(w), [n][c][re/im][f]

// ---------------------------------------------------------------------------
// Kernel 1: partial accumulation of nume = sum_t x * s and den = sum_t |s|^2,
// where s_t = sum_e conj(x_e[t]) d_e.  (phi never materialized.)
// Depth-2 software pipeline over t (32 loads in flight per thread).
// grid: (ceil(NB*FF/128), TS), block 128. One thread per (n,f,z).
// ---------------------------------------------------------------------------
__global__ void snum_kernel(const float* __restrict__ x,
                            const float* __restrict__ sv) {
    int id = blockIdx.x * 128 + threadIdx.x;  // over NB*FF
    int z = blockIdx.y;
    if (id >= NB * FF) return;
    int n = id / FF;
    int f = id - n * FF;

    // steering vector d[f][c], layout [2, F, C, 1]
    float dr[CC], di[CC];
#pragma unroll
    for (int c = 0; c < CC; ++c) {
        dr[c] = sv[(size_t)(0 * FF + f) * CC + c];
        di[c] = sv[(size_t)(1 * FF + f) * CC + c];
    }

    float numr[CC], numi[CC], den = 0.f;
#pragma unroll
    for (int c = 0; c < CC; ++c) { numr[c] = 0.f; numi[c] = 0.f; }

    const size_t chanStride = (size_t)TT * FF;
    const float* xr = x + (size_t)(n * 2 + 0) * CC * chanStride + f;
    const float* xi = x + (size_t)(n * 2 + 1) * CC * chanStride + f;

    int t0 = z * TCH;
    float a[2][CC], b[2][CC];
#pragma unroll
    for (int s = 0; s < 2; ++s) {
        size_t toff = (size_t)(t0 + s) * FF;
#pragma unroll
        for (int c = 0; c < CC; ++c) {
            a[s][c] = xr[(size_t)c * chanStride + toff];
            b[s][c] = xi[(size_t)c * chanStride + toff];
        }
    }

#pragma unroll 2
    for (int i = 0; i < TCH; ++i) {
        const int s = i & 1;
        float na[CC], nb[CC];
        if (i < TCH - 2) {
            size_t toff2 = (size_t)(t0 + i + 2) * FF;
#pragma unroll
            for (int c = 0; c < CC; ++c) {
                na[c] = xr[(size_t)c * chanStride + toff2];
                nb[c] = xi[(size_t)c * chanStride + toff2];
            }
        }

        // s_t = sum_c conj(x_c) d_c
        float sr = 0.f, si = 0.f;
#pragma unroll
        for (int c = 0; c < CC; ++c) {
            sr += a[s][c] * dr[c] + b[s][c] * di[c];
            si += a[s][c] * di[c] - b[s][c] * dr[c];
        }
        den += sr * sr + si * si;
        // nume_c += x_c * s_t
#pragma unroll
        for (int c = 0; c < CC; ++c) {
            numr[c] += a[s][c] * sr - b[s][c] * si;
            numi[c] += a[s][c] * si + b[s][c] * sr;
        }

        if (i < TCH - 2) {
#pragma unroll
            for (int c = 0; c < CC; ++c) { a[s][c] = na[c]; b[s][c] = nb[c]; }
        }
    }

    float* pb = g_part + ((size_t)(z * NB + n) * NP) * FF + f;
#pragma unroll
    for (int c = 0; c < CC; ++c) {
        pb[(size_t)c * FF] = numr[c];
        pb[(size_t)(8 + c) * FF] = numi[c];
    }
    pb[(size_t)16 * FF] = den;
}

// ---------------------------------------------------------------------------
// Kernel 2: warp per (n,f). Lane z loads that chunk's 17 partials; butterfly
// shuffle reduction; lane 0 applies loading and solves for conj(w).
// ---------------------------------------------------------------------------
__global__ void __launch_bounds__(256) weight_kernel(const float* __restrict__ sv) {
    int gw = (blockIdx.x * 256 + threadIdx.x) >> 5;  // global warp id
    int lane = threadIdx.x & 31;
    if (gw >= NB * FF) return;
    int n = gw / FF;
    int f = gw - n * FF;

    float v[NP];
    if (lane < TS) {
        const float* pb = g_part + ((size_t)(lane * NB + n) * NP) * FF + f;
#pragma unroll
        for (int k = 0; k < NP; ++k) v[k] = pb[(size_t)k * FF];
    } else {
#pragma unroll
        for (int k = 0; k < NP; ++k) v[k] = 0.f;
    }

#pragma unroll
    for (int off = 16; off >= 1; off >>= 1) {
#pragma unroll
        for (int k = 0; k < NP; ++k)
            v[k] += __shfl_down_sync(0xffffffffu, v[k], off);
    }

    if (lane != 0) return;

    const float invT = 1.0f / (float)TT;
    const float LOADC = 0.001f * 0.7071067811865475f;  // 0.001/sqrt(2)

    float dr[CC], di[CC];
    float dd = 0.f;
#pragma unroll
    for (int c = 0; c < CC; ++c) {
        dr[c] = sv[(size_t)(0 * FF + f) * CC + c];
        di[c] = sv[(size_t)(1 * FF + f) * CC + c];
        dd += dr[c] * dr[c] + di[c] * di[c];
    }

    // nume_c = invT*sum + LOAD*(1+i)*d_c
    float nr[CC], ni[CC];
#pragma unroll
    for (int c = 0; c < CC; ++c) {
        nr[c] = v[c] * invT + LOADC * (dr[c] - di[c]);
        ni[c] = v[8 + c] * invT + LOADC * (dr[c] + di[c]);
    }
    // deno = invT*sum|s|^2 + LOAD*(1+i)*||d||^2
    float der = v[16] * invT + LOADC * dd;
    float dei = LOADC * dd;
    float inv = 1.0f / (der * der + dei * dei);

#pragma unroll
    for (int c = 0; c < CC; ++c) {
        float wr = (nr[c] * der + ni[c] * dei) * inv;
        float wi = (ni[c] * der - nr[c] * dei) * inv;
        g_w[((size_t)(n * CC + c) * 2 + 0) * FF + f] = wr;   // re(conj w)
        g_w[((size_t)(n * CC + c) * 2 + 1) * FF + f] = -wi;  // im(conj w)
    }
}

// ---------------------------------------------------------------------------
// Kernel 3: beamform mixture with conj(w). Depth-2 software pipeline
// (round-4 configuration — the measured best for this kernel).
// grid: (ceil(F/128), T/TB, N), block 128.
// ---------------------------------------------------------------------------
#define TB 8
__global__ void bf_kernel(const float* __restrict__ y,
                          float* __restrict__ out) {
    int f = blockIdx.x * 128 + threadIdx.x;
    int n = blockIdx.z;
    int t0 = blockIdx.y * TB;
    if (f >= FF) return;

    float cwr[CC], cwi[CC];
#pragma unroll
    for (int c = 0; c < CC; ++c) {
        cwr[c] = g_w[((size_t)(n * CC + c) * 2 + 0) * FF + f];
        cwi[c] = g_w[((size_t)(n * CC + c) * 2 + 1) * FF + f];
    }

    const size_t chanStride = (size_t)TT * FF;
    const float* yr = y + (size_t)(n * 2 + 0) * CC * chanStride + f;
    const float* yi = y + (size_t)(n * 2 + 1) * CC * chanStride + f;
    float* outr = out + (size_t)(n * 2 + 0) * TT * FF + f;
    float* outi = out + (size_t)(n * 2 + 1) * TT * FF + f;

    float a[2][CC], b[2][CC];
#pragma unroll
    for (int s = 0; s < 2; ++s) {
        size_t toff = (size_t)(t0 + s) * FF;
#pragma unroll
        for (int c = 0; c < CC; ++c) {
            a[s][c] = yr[(size_t)c * chanStride + toff];
            b[s][c] = yi[(size_t)c * chanStride + toff];
        }
    }

#pragma unroll
    for (int i = 0; i < TB; ++i) {
        const int s = i & 1;
        float na[CC], nb[CC];
        if (i < TB - 2) {
            size_t toff2 = (size_t)(t0 + i + 2) * FF;
#pragma unroll
            for (int c = 0; c < CC; ++c) {
                na[c] = yr[(size_t)c * chanStride + toff2];
                nb[c] = yi[(size_t)c * chanStride + toff2];
            }
        }

        float ar = 0.f, ai = 0.f;
#pragma unroll
        for (int c = 0; c < CC; ++c) {
            ar += cwr[c] * a[s][c] - cwi[c] * b[s][c];
            ai += cwr[c] * b[s][c] + cwi[c] * a[s][c];
        }
        size_t toff = (size_t)(t0 + i) * FF;
        outr[toff] = ar;
        outi[toff] = ai;

        if (i < TB - 2) {
#pragma unroll
            for (int c = 0; c < CC; ++c) { a[s][c] = na[c]; b[s][c] = nb[c]; }
        }
    }
}

extern "C" void kernel_launch(void* const* d_in, const int* in_sizes, int n_in,
                              void* d_out, int out_size) {
    const float* mixture = (const float*)d_in[0];
    // d_in[1] = noise (unused by the reference computation)
    const float* target = (const float*)d_in[2];
    const float* sv = (const float*)d_in[3];
    float* out = (float*)d_out;

    int nth = NB * FF;  // 4104
    dim3 gA((nth + 127) / 128, TS);
    snum_kernel<<<gA, 128>>>(target, sv);

    int nwarps = nth;  // one warp per (n,f)
    weight_kernel<<<(nwarps * 32 + 255) / 256, 256>>>(sv);

    dim3 gC((FF + 127) / 128, TT / TB, NB);
    bf_kernel<<<gC, 128>>>(mixture, out);
}